// round 5
// baseline (speedup 1.0000x reference)
#include <cuda_runtime.h>
#include <cuda_fp16.h>
#include <math.h>

// Problem constants: N=100000, D=128, E=1600000
#define NMAX 100000
#define DD   128
#define EMAX 1600000
#define NB   1184          // 8 blocks/SM * 148 SMs (GB300 has 152 -> still all-resident)
#define TPB  256
#define WPB  (TPB / 32)
#define NWARPS (NB * WPB)
#define NTHREADS (NB * TPB)

// Static device scratch (no allocations)
__device__ __half g_srch[NMAX * DD];   // fp16 src table (row = 256 B = 16 uint4)
__device__ __half g_dsth[NMAX * DD];   // fp16 dst table
__device__ float  g_lik[EMAX];         // likelihood (k_edge -> k_post)
__device__ double g_p1[NB], g_p2[NB], g_p3[NB];
__device__ unsigned g_bar;             // grid barrier arrival counter (monotonic)

// ---------------------------------------------------------------------------
// K0: fp32 -> fp16 table conversion (streaming, DRAM-bound)
// ---------------------------------------------------------------------------
__global__ __launch_bounds__(TPB) void k_conv(
    const float* __restrict__ src, const float* __restrict__ dst, int total)
{
    const int nt4 = total >> 2;
    const float4* __restrict__ s4 = (const float4*)src;
    const float4* __restrict__ d4 = (const float4*)dst;
    uint2* __restrict__ so = (uint2*)g_srch;
    uint2* __restrict__ dsto = (uint2*)g_dsth;

    for (int i = blockIdx.x * TPB + threadIdx.x; i < nt4; i += NTHREADS) {
        float4 v = __ldcs(s4 + i);
        union { __half2 h; unsigned u; } c0, c1;
        c0.h = __floats2half2_rn(v.x, v.y);
        c1.h = __floats2half2_rn(v.z, v.w);
        so[i] = make_uint2(c0.u, c1.u);

        float4 w = __ldcs(d4 + i);
        c0.h = __floats2half2_rn(w.x, w.y);
        c1.h = __floats2half2_rn(w.z, w.w);
        dsto[i] = make_uint2(c0.u, c1.u);
    }
}

// ---------------------------------------------------------------------------
// K1: gather + squared distance + likelihood + partial stats.
// 16 lanes per edge (uint4 = 16B covers 256B fp16 row), 2 edges per warp-step.
// ---------------------------------------------------------------------------
__global__ __launch_bounds__(TPB) void k_edge(
    const int* __restrict__ gr, int E, int Nn)
{
    const int lane  = threadIdx.x & 31;
    const int gwarp = (blockIdx.x * TPB + threadIdx.x) >> 5;
    const int half_sel = lane & 16;
    const int lane15   = lane & 15;

    const uint4* __restrict__ stab = (const uint4*)g_srch;
    const uint4* __restrict__ dtab = (const uint4*)g_dsth;

    double a1 = 0.0, a2 = 0.0;

    for (int base = gwarp * 32; base < E; base += NWARPS * 32) {
        const int m = min(32, E - base);
        const int e = base + lane;

        int si = 0, di = 0;
        if (lane < m) {
            si = __ldcs(gr + e);
            di = __ldcs(gr + (size_t)E + e);
        }
        si = min(max(si, 0), Nn - 1);
        di = min(max(di, 0), Nn - 1);

        float acc = 0.0f;

        #pragma unroll 4
        for (int t = 0; t < 16; t++) {
            const int srcl = t | half_sel;
            const int s = __shfl_sync(0xffffffffu, si, srcl);
            const int d = __shfl_sync(0xffffffffu, di, srcl);

            uint4 av = __ldg(stab + (size_t)s * 16 + lane15);
            uint4 bv = __ldg(dtab + (size_t)d * 16 + lane15);
            const __half2* ah = (const __half2*)&av;
            const __half2* bh = (const __half2*)&bv;

            float p = 0.0f;
            #pragma unroll
            for (int i = 0; i < 4; i++) {
                float2 fa = __half22float2(ah[i]);
                float2 fb = __half22float2(bh[i]);
                float dx = fa.x - fb.x, dy = fa.y - fb.y;
                p = fmaf(dx, dx, fmaf(dy, dy, p));
            }
            #pragma unroll
            for (int o = 8; o; o >>= 1)
                p += __shfl_xor_sync(0xffffffffu, p, o);

            if (lane15 == t) acc = p;
        }

        if (lane < m) {
            float v = -__logf(fmaxf(acc, 1e-12f));
            __stcs(g_lik + e, v);
            a1 += (double)v;
            a2 += (double)v * (double)v;
        }
    }

    __shared__ double sh1[TPB], shq[TPB];
    sh1[threadIdx.x] = a1; shq[threadIdx.x] = a2;
    __syncthreads();
    for (int st = TPB / 2; st; st >>= 1) {
        if (threadIdx.x < st) {
            sh1[threadIdx.x] += sh1[threadIdx.x + st];
            shq[threadIdx.x] += shq[threadIdx.x + st];
        }
        __syncthreads();
    }
    if (threadIdx.x == 0) { g_p1[blockIdx.x] = sh1[0]; g_p2[blockIdx.x] = shq[0]; }
}

// ---------------------------------------------------------------------------
// K2 (persistent, grid-barrier): mu/std finalize + logits + sigmoid (kept in
// registers) + graph copy (hides barrier wait) + grid sync + ew normalize.
// Grid is exactly all-resident: 1184 blocks, <=32 regs forced by launch bounds.
// ---------------------------------------------------------------------------
__global__ __launch_bounds__(TPB, 8) void k_post(
    const int* __restrict__ gr,
    const float* __restrict__ bw, const float* __restrict__ bb,
    float* __restrict__ out, int E)
{
    __shared__ double sh1[TPB], shq[TPB];

    // --- finalize mu / inv_std (redundant per block; partials broadcast from L2)
    double t1 = 0.0, t2 = 0.0;
    for (int i = threadIdx.x; i < NB; i += TPB) { t1 += g_p1[i]; t2 += g_p2[i]; }
    sh1[threadIdx.x] = t1; shq[threadIdx.x] = t2;
    __syncthreads();
    for (int st = TPB / 2; st; st >>= 1) {
        if (threadIdx.x < st) {
            sh1[threadIdx.x] += sh1[threadIdx.x + st];
            shq[threadIdx.x] += shq[threadIdx.x + st];
        }
        __syncthreads();
    }
    __shared__ float s_mu, s_inv;
    if (threadIdx.x == 0) {
        double mu  = sh1[0] / (double)E;
        double var = shq[0] / (double)E - mu * mu;
        s_mu  = (float)mu;
        s_inv = (float)rsqrt(var + 1e-5);
    }
    __syncthreads();

    const float mu = s_mu, inv = s_inv;
    const float wi = __ldg(bw) * inv;
    const float b  = __ldg(bb);

    float4* __restrict__ lik4 = (float4*)g_lik;
    float4* __restrict__ lg4  = (float4*)(out + 3LL * E);

    const int E4  = E >> 2;
    const int tid = blockIdx.x * TPB + threadIdx.x;

    // --- logits + sigmoid; sigmoid kept in registers (<=2 chunks per thread)
    float4 keep[2];
    double s = 0.0;
    int c = 0;
    for (int i = tid; i < E4; i += NTHREADS, c++) {
        float4 l = lik4[i];
        float4 g;
        g.x = fmaf(wi, l.x - mu, b);
        g.y = fmaf(wi, l.y - mu, b);
        g.z = fmaf(wi, l.z - mu, b);
        g.w = fmaf(wi, l.w - mu, b);
        __stcs(lg4 + i, g);
        float4 sg;
        sg.x = 1.0f / (1.0f + __expf(-g.x));
        sg.y = 1.0f / (1.0f + __expf(-g.y));
        sg.z = 1.0f / (1.0f + __expf(-g.z));
        sg.w = 1.0f / (1.0f + __expf(-g.w));
        if (c < 2) keep[c] = sg; else lik4[i] = sg;   // register fast path
        s += (double)((sg.x + sg.y) + (sg.z + sg.w));
    }
    for (int e = E4 * 4 + tid; e < E; e += NTHREADS) {   // scalar tail
        float lg = fmaf(wi, g_lik[e] - mu, b);
        out[3LL * E + e] = lg;
        float sg = 1.0f / (1.0f + __expf(-lg));
        g_lik[e] = sg;
        s += (double)sg;
    }

    // --- block partial of sigmoid sum, then arrive at grid barrier
    sh1[threadIdx.x] = s;
    __syncthreads();
    for (int st = TPB / 2; st; st >>= 1) {
        if (threadIdx.x < st) sh1[threadIdx.x] += sh1[threadIdx.x + st];
        __syncthreads();
    }
    __shared__ unsigned s_target;
    if (threadIdx.x == 0) {
        g_p3[blockIdx.x] = sh1[0];
        __threadfence();
        unsigned old = atomicAdd(&g_bar, 1u);
        s_target = old - (old % NB) + NB;      // replay-safe launch target
    }

    // --- graph -> float copy (useful work that hides barrier wait)
    const int E2 = 2 * E;
    for (int i = tid; i < E2; i += NTHREADS)
        __stcs(out + i, (float)__ldcs(gr + i));

    __syncthreads();
    if (threadIdx.x == 0) {
        volatile unsigned* vb = &g_bar;
        while (*vb < s_target) { }
        __threadfence();
    }
    __syncthreads();

    // --- finalize inv_mean (redundant per block)
    double t = 0.0;
    for (int i = threadIdx.x; i < NB; i += TPB) t += g_p3[i];
    sh1[threadIdx.x] = t;
    __syncthreads();
    for (int st = TPB / 2; st; st >>= 1) {
        if (threadIdx.x < st) sh1[threadIdx.x] += sh1[threadIdx.x + st];
        __syncthreads();
    }
    __shared__ float s_im;
    if (threadIdx.x == 0) s_im = (float)((double)E / sh1[0]);
    __syncthreads();
    const float im = s_im;

    // --- normalized edge weights from registers
    float4* __restrict__ ew4 = (float4*)(out + 2LL * E);
    c = 0;
    for (int i = tid; i < E4; i += NTHREADS, c++) {
        float4 v = (c < 2) ? keep[c] : lik4[i];
        v.x *= im; v.y *= im; v.z *= im; v.w *= im;
        __stcs(ew4 + i, v);
    }
    for (int e = E4 * 4 + tid; e < E; e += NTHREADS)
        out[2LL * E + e] = g_lik[e] * im;
}

// ---------------------------------------------------------------------------
extern "C" void kernel_launch(void* const* d_in, const int* in_sizes, int n_in,
                              void* d_out, int out_size)
{
    const float* src = (const float*)d_in[0];
    const float* dst = (const float*)d_in[1];
    const int*   gr  = (const int*)d_in[2];
    const float* bw  = (const float*)d_in[3];
    const float* bb  = (const float*)d_in[4];
    float* out = (float*)d_out;

    const int E  = in_sizes[2] / 2;
    const int Nn = in_sizes[0] / DD;
    const int total = min(in_sizes[0], NMAX * DD);

    k_conv<<<NB, TPB>>>(src, dst, total);
    k_edge<<<NB, TPB>>>(gr, E, Nn);
    k_post<<<NB, TPB>>>(gr, bw, bb, out, E);
}

// round 6
// speedup vs baseline: 1.1000x; 1.1000x over previous
#include <cuda_runtime.h>
#include <cuda_fp16.h>
#include <math.h>

// Problem constants: N=100000, D=128, E=1600000
#define NMAX 100000
#define DD   128
#define EMAX 1600000
#define NB   1184          // main grid: 8 blocks/SM * 148
#define TPB  256
#define NTHREADS (NB * TPB)

#define NB2  296           // tail grid: 2 blocks/SM * 148
#define TPB2 512
#define NT2  (NB2 * TPB2)  // 151552

// Static device scratch (no allocations)
__device__ __half g_srch[NMAX * DD];   // fp16 src table (row = 256 B = 16 uint4)
__device__ __half g_dsth[NMAX * DD];   // fp16 dst table
__device__ float  g_lik[EMAX];         // likelihood (k_edge -> k_logits)
__device__ double g_p1[NB], g_p2[NB];  // lik partials
__device__ double g_p3[NB2];           // sigmoid partials

// ---------------------------------------------------------------------------
// K0: fp32 -> fp16 tables (uint4 stores) + graph -> float output copy.
// All streaming, DRAM-bound; copy is independent of conversion.
// ---------------------------------------------------------------------------
__global__ __launch_bounds__(TPB) void k_conv(
    const float* __restrict__ src, const float* __restrict__ dst,
    const int* __restrict__ gr, float* __restrict__ out, int total, int E2)
{
    const int nt8 = total >> 3;
    const float4* __restrict__ s4 = (const float4*)src;
    const float4* __restrict__ d4 = (const float4*)dst;
    uint4* __restrict__ so = (uint4*)g_srch;
    uint4* __restrict__ dsto = (uint4*)g_dsth;

    const int tid = blockIdx.x * TPB + threadIdx.x;

    for (int i = tid; i < nt8; i += NTHREADS) {
        float4 a0 = __ldcs(s4 + 2 * i);
        float4 a1 = __ldcs(s4 + 2 * i + 1);
        union { __half2 h; unsigned u; } c;
        uint4 o;
        c.h = __floats2half2_rn(a0.x, a0.y); o.x = c.u;
        c.h = __floats2half2_rn(a0.z, a0.w); o.y = c.u;
        c.h = __floats2half2_rn(a1.x, a1.y); o.z = c.u;
        c.h = __floats2half2_rn(a1.z, a1.w); o.w = c.u;
        __stcs(so + i, o);

        float4 b0 = __ldcs(d4 + 2 * i);
        float4 b1 = __ldcs(d4 + 2 * i + 1);
        c.h = __floats2half2_rn(b0.x, b0.y); o.x = c.u;
        c.h = __floats2half2_rn(b0.z, b0.w); o.y = c.u;
        c.h = __floats2half2_rn(b1.x, b1.y); o.z = c.u;
        c.h = __floats2half2_rn(b1.z, b1.w); o.w = c.u;
        __stcs(dsto + i, o);
    }

    for (int i = tid; i < E2; i += NTHREADS)
        __stcs(out + i, (float)__ldcs(gr + i));
}

// ---------------------------------------------------------------------------
// K1: gather + squared distance + likelihood + partial stats.
// 16 lanes per edge (uint4 = 16B covers 256B fp16 row), 2 edges per warp-step.
// ---------------------------------------------------------------------------
__global__ __launch_bounds__(TPB) void k_edge(
    const int* __restrict__ gr, int E, int Nn)
{
    const int lane  = threadIdx.x & 31;
    const int gwarp = (blockIdx.x * TPB + threadIdx.x) >> 5;
    const int half_sel = lane & 16;
    const int lane15   = lane & 15;
    const int nwarps = NTHREADS / 32;

    const uint4* __restrict__ stab = (const uint4*)g_srch;
    const uint4* __restrict__ dtab = (const uint4*)g_dsth;

    double a1 = 0.0, a2 = 0.0;

    for (int base = gwarp * 32; base < E; base += nwarps * 32) {
        const int m = min(32, E - base);
        const int e = base + lane;

        int si = 0, di = 0;
        if (lane < m) {
            si = __ldcs(gr + e);
            di = __ldcs(gr + (size_t)E + e);
        }
        si = min(max(si, 0), Nn - 1);
        di = min(max(di, 0), Nn - 1);

        float acc = 0.0f;

        #pragma unroll 4
        for (int t = 0; t < 16; t++) {
            const int srcl = t | half_sel;
            const int s = __shfl_sync(0xffffffffu, si, srcl);
            const int d = __shfl_sync(0xffffffffu, di, srcl);

            uint4 av = __ldg(stab + (size_t)s * 16 + lane15);
            uint4 bv = __ldg(dtab + (size_t)d * 16 + lane15);
            const __half2* ah = (const __half2*)&av;
            const __half2* bh = (const __half2*)&bv;

            float p = 0.0f;
            #pragma unroll
            for (int i = 0; i < 4; i++) {
                float2 fa = __half22float2(ah[i]);
                float2 fb = __half22float2(bh[i]);
                float dx = fa.x - fb.x, dy = fa.y - fb.y;
                p = fmaf(dx, dx, fmaf(dy, dy, p));
            }
            #pragma unroll
            for (int o = 8; o; o >>= 1)
                p += __shfl_xor_sync(0xffffffffu, p, o);

            if (lane15 == t) acc = p;
        }

        if (lane < m) {
            float v = -__logf(fmaxf(acc, 1e-12f));
            __stcs(g_lik + e, v);
            a1 += (double)v;
            a2 += (double)v * (double)v;
        }
    }

    __shared__ double sh1[TPB], shq[TPB];
    sh1[threadIdx.x] = a1; shq[threadIdx.x] = a2;
    __syncthreads();
    for (int st = TPB / 2; st; st >>= 1) {
        if (threadIdx.x < st) {
            sh1[threadIdx.x] += sh1[threadIdx.x + st];
            shq[threadIdx.x] += shq[threadIdx.x + st];
        }
        __syncthreads();
    }
    if (threadIdx.x == 0) { g_p1[blockIdx.x] = sh1[0]; g_p2[blockIdx.x] = shq[0]; }
}

// ---------------------------------------------------------------------------
// K2: mu/inv_std finalize + logits (stored) + sigmoid partial sums.
// Batch-of-3 strided loads for MLP; sigmoid NOT stored (recomputed in K3).
// ---------------------------------------------------------------------------
__global__ __launch_bounds__(TPB2, 2) void k_logits(
    const float* __restrict__ bw, const float* __restrict__ bb,
    float* __restrict__ out, int E)
{
    __shared__ double sh1[TPB2], shq[TPB2];
    double t1 = 0.0, t2 = 0.0;
    for (int i = threadIdx.x; i < NB; i += TPB2) { t1 += g_p1[i]; t2 += g_p2[i]; }
    sh1[threadIdx.x] = t1; shq[threadIdx.x] = t2;
    __syncthreads();
    for (int st = TPB2 / 2; st; st >>= 1) {
        if (threadIdx.x < st) {
            sh1[threadIdx.x] += sh1[threadIdx.x + st];
            shq[threadIdx.x] += shq[threadIdx.x + st];
        }
        __syncthreads();
    }
    __shared__ float s_mu, s_inv;
    if (threadIdx.x == 0) {
        double mu  = sh1[0] / (double)E;
        double var = shq[0] / (double)E - mu * mu;
        s_mu  = (float)mu;
        s_inv = (float)rsqrt(var + 1e-5);
    }
    __syncthreads();

    const float mu = s_mu;
    const float wi = __ldg(bw) * s_inv;
    const float b  = __ldg(bb);

    const float4* __restrict__ lik4 = (const float4*)g_lik;
    float4* __restrict__ lg4 = (float4*)(out + 3LL * E);

    const int E4  = E >> 2;
    const int tid = blockIdx.x * TPB2 + threadIdx.x;
    double s = 0.0;

    for (int i0 = tid; i0 < E4; i0 += 3 * NT2) {
        const int i1 = i0 + NT2, i2 = i0 + 2 * NT2;
        float4 l0, l1, l2;
        l0 = lik4[i0];                       // 3 independent loads in flight
        if (i1 < E4) l1 = lik4[i1];
        if (i2 < E4) l2 = lik4[i2];

        float4 g;
        g.x = fmaf(wi, l0.x - mu, b); g.y = fmaf(wi, l0.y - mu, b);
        g.z = fmaf(wi, l0.z - mu, b); g.w = fmaf(wi, l0.w - mu, b);
        __stcs(lg4 + i0, g);
        s += (double)((1.0f / (1.0f + __expf(-g.x)) + 1.0f / (1.0f + __expf(-g.y))) +
                      (1.0f / (1.0f + __expf(-g.z)) + 1.0f / (1.0f + __expf(-g.w))));
        if (i1 < E4) {
            g.x = fmaf(wi, l1.x - mu, b); g.y = fmaf(wi, l1.y - mu, b);
            g.z = fmaf(wi, l1.z - mu, b); g.w = fmaf(wi, l1.w - mu, b);
            __stcs(lg4 + i1, g);
            s += (double)((1.0f / (1.0f + __expf(-g.x)) + 1.0f / (1.0f + __expf(-g.y))) +
                          (1.0f / (1.0f + __expf(-g.z)) + 1.0f / (1.0f + __expf(-g.w))));
        }
        if (i2 < E4) {
            g.x = fmaf(wi, l2.x - mu, b); g.y = fmaf(wi, l2.y - mu, b);
            g.z = fmaf(wi, l2.z - mu, b); g.w = fmaf(wi, l2.w - mu, b);
            __stcs(lg4 + i2, g);
            s += (double)((1.0f / (1.0f + __expf(-g.x)) + 1.0f / (1.0f + __expf(-g.y))) +
                          (1.0f / (1.0f + __expf(-g.z)) + 1.0f / (1.0f + __expf(-g.w))));
        }
    }
    for (int e = E4 * 4 + tid; e < E; e += NT2) {    // scalar tail
        float lg = fmaf(wi, g_lik[e] - mu, b);
        out[3LL * E + e] = lg;
        s += (double)(1.0f / (1.0f + __expf(-lg)));
    }

    sh1[threadIdx.x] = s;
    __syncthreads();
    for (int st = TPB2 / 2; st; st >>= 1) {
        if (threadIdx.x < st) sh1[threadIdx.x] += sh1[threadIdx.x + st];
        __syncthreads();
    }
    if (threadIdx.x == 0) g_p3[blockIdx.x] = sh1[0];
}

// ---------------------------------------------------------------------------
// K3: inv_mean finalize + edge weights (sigmoid recomputed from L2-hot logits)
// ---------------------------------------------------------------------------
__global__ __launch_bounds__(TPB2, 2) void k_ew(float* __restrict__ out, int E)
{
    __shared__ double sh[TPB2];
    double t = 0.0;
    for (int i = threadIdx.x; i < NB2; i += TPB2) t += g_p3[i];
    sh[threadIdx.x] = t;
    __syncthreads();
    for (int st = TPB2 / 2; st; st >>= 1) {
        if (threadIdx.x < st) sh[threadIdx.x] += sh[threadIdx.x + st];
        __syncthreads();
    }
    __shared__ float s_im;
    if (threadIdx.x == 0) s_im = (float)((double)E / sh[0]);
    __syncthreads();
    const float im = s_im;

    const float4* __restrict__ lg4 = (const float4*)(out + 3LL * E);
    float4* __restrict__ ew4 = (float4*)(out + 2LL * E);

    const int E4  = E >> 2;
    const int tid = blockIdx.x * TPB2 + threadIdx.x;

    for (int i0 = tid; i0 < E4; i0 += 3 * NT2) {
        const int i1 = i0 + NT2, i2 = i0 + 2 * NT2;
        float4 g0, g1, g2;
        g0 = __ldcs(lg4 + i0);
        if (i1 < E4) g1 = __ldcs(lg4 + i1);
        if (i2 < E4) g2 = __ldcs(lg4 + i2);

        float4 v;
        v.x = im / (1.0f + __expf(-g0.x)); v.y = im / (1.0f + __expf(-g0.y));
        v.z = im / (1.0f + __expf(-g0.z)); v.w = im / (1.0f + __expf(-g0.w));
        __stcs(ew4 + i0, v);
        if (i1 < E4) {
            v.x = im / (1.0f + __expf(-g1.x)); v.y = im / (1.0f + __expf(-g1.y));
            v.z = im / (1.0f + __expf(-g1.z)); v.w = im / (1.0f + __expf(-g1.w));
            __stcs(ew4 + i1, v);
        }
        if (i2 < E4) {
            v.x = im / (1.0f + __expf(-g2.x)); v.y = im / (1.0f + __expf(-g2.y));
            v.z = im / (1.0f + __expf(-g2.z)); v.w = im / (1.0f + __expf(-g2.w));
            __stcs(ew4 + i2, v);
        }
    }
    for (int e = E4 * 4 + tid; e < E; e += NT2)
        out[2LL * E + e] = im / (1.0f + __expf(-out[3LL * E + e]));
}

// ---------------------------------------------------------------------------
extern "C" void kernel_launch(void* const* d_in, const int* in_sizes, int n_in,
                              void* d_out, int out_size)
{
    const float* src = (const float*)d_in[0];
    const float* dst = (const float*)d_in[1];
    const int*   gr  = (const int*)d_in[2];
    const float* bw  = (const float*)d_in[3];
    const float* bb  = (const float*)d_in[4];
    float* out = (float*)d_out;

    const int E  = in_sizes[2] / 2;
    const int Nn = in_sizes[0] / DD;
    const int total = min(in_sizes[0], NMAX * DD);

    k_conv  <<<NB,  TPB >>>(src, dst, gr, out, total, 2 * E);
    k_edge  <<<NB,  TPB >>>(gr, E, Nn);
    k_logits<<<NB2, TPB2>>>(bw, bb, out, E);
    k_ew    <<<NB2, TPB2>>>(out, E);
}

// round 7
// speedup vs baseline: 1.1034x; 1.0030x over previous
#include <cuda_runtime.h>
#include <cuda_fp16.h>
#include <math.h>

// Problem constants: N=100000, D=128, E=1600000
#define NMAX 100000
#define DD   128
#define EMAX 1600000
#define NB   1184          // main grid: 8 blocks/SM * 148
#define TPB  256
#define NTHREADS (NB * TPB)

#define NB3  1184          // tail grids: full occupancy
#define TPB3 256
#define NT3  (NB3 * TPB3)

// Static device scratch (no allocations)
__device__ __half g_srch[NMAX * DD];   // fp16 src table (row = 256 B = 16 uint4)
__device__ __half g_dsth[NMAX * DD];   // fp16 dst table
__device__ float  g_lik[EMAX];         // likelihood (k_edge -> k_logits)
__device__ double g_p1[NB], g_p2[NB];  // lik partials
__device__ double g_p3[NB3];           // sigmoid partials
__device__ float  g_mu, g_inv;         // published by k_edge's last block
__device__ float  g_im;                // published by k_logits' last block
__device__ unsigned g_c1, g_c2;        // monotonic arrival counters (replay-safe)

// ---------------------------------------------------------------------------
// K0: fp32 -> fp16 tables (uint4 stores, L2-resident via .cg) + graph copy.
// ---------------------------------------------------------------------------
__global__ __launch_bounds__(TPB) void k_conv(
    const float* __restrict__ src, const float* __restrict__ dst,
    const int* __restrict__ gr, float* __restrict__ out, int total, int E2)
{
    const int nt8 = total >> 3;
    const float4* __restrict__ s4 = (const float4*)src;
    const float4* __restrict__ d4 = (const float4*)dst;
    uint4* __restrict__ so = (uint4*)g_srch;
    uint4* __restrict__ dsto = (uint4*)g_dsth;

    const int tid = blockIdx.x * TPB + threadIdx.x;

    for (int i = tid; i < nt8; i += NTHREADS) {
        float4 a0 = __ldcs(s4 + 2 * i);
        float4 a1 = __ldcs(s4 + 2 * i + 1);
        union { __half2 h; unsigned u; } c;
        uint4 o;
        c.h = __floats2half2_rn(a0.x, a0.y); o.x = c.u;
        c.h = __floats2half2_rn(a0.z, a0.w); o.y = c.u;
        c.h = __floats2half2_rn(a1.x, a1.y); o.z = c.u;
        c.h = __floats2half2_rn(a1.z, a1.w); o.w = c.u;
        __stcg(so + i, o);                       // keep table L2-resident

        float4 b0 = __ldcs(d4 + 2 * i);
        float4 b1 = __ldcs(d4 + 2 * i + 1);
        c.h = __floats2half2_rn(b0.x, b0.y); o.x = c.u;
        c.h = __floats2half2_rn(b0.z, b0.w); o.y = c.u;
        c.h = __floats2half2_rn(b1.x, b1.y); o.z = c.u;
        c.h = __floats2half2_rn(b1.z, b1.w); o.w = c.u;
        __stcg(dsto + i, o);
    }

    for (int i = tid; i < E2; i += NTHREADS)
        __stcs(out + i, (float)__ldcs(gr + i));
}

// ---------------------------------------------------------------------------
// K1: gather + squared distance + likelihood + partial stats; the last block
// to finish reduces all partials and publishes mu / inv_std.
// ---------------------------------------------------------------------------
__global__ __launch_bounds__(TPB) void k_edge(
    const int* __restrict__ gr, int E, int Nn)
{
    const int lane  = threadIdx.x & 31;
    const int gwarp = (blockIdx.x * TPB + threadIdx.x) >> 5;
    const int half_sel = lane & 16;
    const int lane15   = lane & 15;
    const int nwarps = NTHREADS / 32;

    const uint4* __restrict__ stab = (const uint4*)g_srch;
    const uint4* __restrict__ dtab = (const uint4*)g_dsth;

    double a1 = 0.0, a2 = 0.0;

    for (int base = gwarp * 32; base < E; base += nwarps * 32) {
        const int m = min(32, E - base);
        const int e = base + lane;

        int si = 0, di = 0;
        if (lane < m) {
            si = __ldcs(gr + e);
            di = __ldcs(gr + (size_t)E + e);
        }
        si = min(max(si, 0), Nn - 1);
        di = min(max(di, 0), Nn - 1);

        float acc = 0.0f;

        #pragma unroll 4
        for (int t = 0; t < 16; t++) {
            const int srcl = t | half_sel;
            const int s = __shfl_sync(0xffffffffu, si, srcl);
            const int d = __shfl_sync(0xffffffffu, di, srcl);

            uint4 av = __ldg(stab + (size_t)s * 16 + lane15);
            uint4 bv = __ldg(dtab + (size_t)d * 16 + lane15);
            const __half2* ah = (const __half2*)&av;
            const __half2* bh = (const __half2*)&bv;

            float p = 0.0f;
            #pragma unroll
            for (int i = 0; i < 4; i++) {
                float2 fa = __half22float2(ah[i]);
                float2 fb = __half22float2(bh[i]);
                float dx = fa.x - fb.x, dy = fa.y - fb.y;
                p = fmaf(dx, dx, fmaf(dy, dy, p));
            }
            #pragma unroll
            for (int o = 8; o; o >>= 1)
                p += __shfl_xor_sync(0xffffffffu, p, o);

            if (lane15 == t) acc = p;
        }

        if (lane < m) {
            float v = -__logf(fmaxf(acc, 1e-12f));
            __stcs(g_lik + e, v);
            a1 += (double)v;
            a2 += (double)v * (double)v;
        }
    }

    __shared__ double sh1[TPB], shq[TPB];
    sh1[threadIdx.x] = a1; shq[threadIdx.x] = a2;
    __syncthreads();
    for (int st = TPB / 2; st; st >>= 1) {
        if (threadIdx.x < st) {
            sh1[threadIdx.x] += sh1[threadIdx.x + st];
            shq[threadIdx.x] += shq[threadIdx.x + st];
        }
        __syncthreads();
    }
    __shared__ int s_last;
    if (threadIdx.x == 0) {
        g_p1[blockIdx.x] = sh1[0];
        g_p2[blockIdx.x] = shq[0];
        __threadfence();
        unsigned old = atomicAdd(&g_c1, 1u);
        s_last = ((old % NB) == NB - 1);       // replay-safe
    }
    __syncthreads();

    if (s_last) {                              // last block finalizes mu/inv_std
        double t1 = 0.0, t2 = 0.0;
        for (int i = threadIdx.x; i < NB; i += TPB) { t1 += g_p1[i]; t2 += g_p2[i]; }
        sh1[threadIdx.x] = t1; shq[threadIdx.x] = t2;
        __syncthreads();
        for (int st = TPB / 2; st; st >>= 1) {
            if (threadIdx.x < st) {
                sh1[threadIdx.x] += sh1[threadIdx.x + st];
                shq[threadIdx.x] += shq[threadIdx.x + st];
            }
            __syncthreads();
        }
        if (threadIdx.x == 0) {
            double mu  = sh1[0] / (double)E;
            double var = shq[0] / (double)E - mu * mu;
            g_mu  = (float)mu;
            g_inv = (float)rsqrt(var + 1e-5);
        }
    }
}

// ---------------------------------------------------------------------------
// K2: logits (stored) + sigmoid partial sums; last block publishes inv_mean.
// Full-occupancy grid; prologue is a 2-float load.
// ---------------------------------------------------------------------------
__global__ __launch_bounds__(TPB3) void k_logits(
    const float* __restrict__ bw, const float* __restrict__ bb,
    float* __restrict__ out, int E)
{
    const float mu = g_mu;
    const float wi = __ldg(bw) * g_inv;
    const float b  = __ldg(bb);

    const float4* __restrict__ lik4 = (const float4*)g_lik;
    float4* __restrict__ lg4 = (float4*)(out + 3LL * E);

    const int E4  = E >> 2;
    const int tid = blockIdx.x * TPB3 + threadIdx.x;
    double s = 0.0;

    for (int i = tid; i < E4; i += NT3) {
        float4 l = lik4[i];
        float4 g;
        g.x = fmaf(wi, l.x - mu, b); g.y = fmaf(wi, l.y - mu, b);
        g.z = fmaf(wi, l.z - mu, b); g.w = fmaf(wi, l.w - mu, b);
        __stcs(lg4 + i, g);
        s += (double)((1.0f / (1.0f + __expf(-g.x)) + 1.0f / (1.0f + __expf(-g.y))) +
                      (1.0f / (1.0f + __expf(-g.z)) + 1.0f / (1.0f + __expf(-g.w))));
    }
    for (int e = E4 * 4 + tid; e < E; e += NT3) {
        float lg = fmaf(wi, g_lik[e] - mu, b);
        out[3LL * E + e] = lg;
        s += (double)(1.0f / (1.0f + __expf(-lg)));
    }

    __shared__ double sh[TPB3];
    sh[threadIdx.x] = s;
    __syncthreads();
    for (int st = TPB3 / 2; st; st >>= 1) {
        if (threadIdx.x < st) sh[threadIdx.x] += sh[threadIdx.x + st];
        __syncthreads();
    }
    __shared__ int s_last;
    if (threadIdx.x == 0) {
        g_p3[blockIdx.x] = sh[0];
        __threadfence();
        unsigned old = atomicAdd(&g_c2, 1u);
        s_last = ((old % NB3) == NB3 - 1);
    }
    __syncthreads();

    if (s_last) {
        double t = 0.0;
        for (int i = threadIdx.x; i < NB3; i += TPB3) t += g_p3[i];
        sh[threadIdx.x] = t;
        __syncthreads();
        for (int st = TPB3 / 2; st; st >>= 1) {
            if (threadIdx.x < st) sh[threadIdx.x] += sh[threadIdx.x + st];
            __syncthreads();
        }
        if (threadIdx.x == 0) g_im = (float)((double)E / sh[0]);
    }
}

// ---------------------------------------------------------------------------
// K3: edge weights — sigmoid recomputed from L2-hot logits, scaled by inv_mean.
// Prologue is a single float load.
// ---------------------------------------------------------------------------
__global__ __launch_bounds__(TPB3) void k_ew(float* __restrict__ out, int E)
{
    const float im = g_im;

    const float4* __restrict__ lg4 = (const float4*)(out + 3LL * E);
    float4* __restrict__ ew4 = (float4*)(out + 2LL * E);

    const int E4  = E >> 2;
    const int tid = blockIdx.x * TPB3 + threadIdx.x;

    for (int i = tid; i < E4; i += NT3) {
        float4 g = __ldcs(lg4 + i);
        float4 v;
        v.x = im / (1.0f + __expf(-g.x)); v.y = im / (1.0f + __expf(-g.y));
        v.z = im / (1.0f + __expf(-g.z)); v.w = im / (1.0f + __expf(-g.w));
        __stcs(ew4 + i, v);
    }
    for (int e = E4 * 4 + tid; e < E; e += NT3)
        out[2LL * E + e] = im / (1.0f + __expf(-out[3LL * E + e]));
}

// ---------------------------------------------------------------------------
extern "C" void kernel_launch(void* const* d_in, const int* in_sizes, int n_in,
                              void* d_out, int out_size)
{
    const float* src = (const float*)d_in[0];
    const float* dst = (const float*)d_in[1];
    const int*   gr  = (const int*)d_in[2];
    const float* bw  = (const float*)d_in[3];
    const float* bb  = (const float*)d_in[4];
    float* out = (float*)d_out;

    const int E  = in_sizes[2] / 2;
    const int Nn = in_sizes[0] / DD;
    const int total = min(in_sizes[0], NMAX * DD);

    k_conv  <<<NB,  TPB >>>(src, dst, gr, out, total, 2 * E);
    k_edge  <<<NB,  TPB >>>(gr, E, Nn);
    k_logits<<<NB3, TPB3>>>(bw, bb, out, E);
    k_ew    <<<NB3, TPB3>>>(out, E);
}